// round 8
// baseline (speedup 1.0000x reference)
#include <cuda_runtime.h>
#include <math.h>
#include <stdint.h>

#define NN 30000
#define TT 4
#define FIN 256
#define HH 64
#define HEADS 4
#define DD 256
#define EE 240000
#define ETOT 270000            // EE + NN self loops
#define NEG_SLOPE 0.2f
#define NB_SCAN 118            // ceil(NN/256)
#define ESZ (TT * NN * HEADS)

// ---------------- scratch (device globals: allocation-free) ----------------
__device__ __align__(16) float g_hp[TT * NN * DD];     // per-layer hp = h @ W
__device__ __align__(16) float g_bufA[TT * NN * DD];   // layer0 output (post ELU)
__device__ __align__(16) float g_bufB[TT * NN * DD];   // layer1 output (embs)
__device__ __align__(16) float g_esed[2 * ESZ];        // es at 0, ed at ESZ
__device__ __align__(16) float g_colsum[TT * DD];
__device__ __align__(16) float g_wf[(FIN + 1) * DD];   // fused Wp@W0 (+ bias row)
__device__ float g_attn[TT];
// CSR
__device__ int g_deg[NN];
__device__ int g_off[NN];
__device__ int g_cursor[NN];
__device__ int g_part[256];
__device__ int g_srcs[ETOT];

// ---------------- utility ----------------
__global__ void zero_kernel(float4* __restrict__ p, int n4) {
    int i = blockIdx.x * blockDim.x + threadIdx.x;
    if (i < n4) p[i] = make_float4(0.f, 0.f, 0.f, 0.f);
}

__device__ __forceinline__ float eluf(float x) { return x > 0.f ? x : expm1f(x); }

__device__ __forceinline__ uint32_t f2tf32(float x) {
    uint32_t r;
    asm("cvt.rna.tf32.f32 %0, %1;" : "=r"(r) : "f"(x));
    return r;
}

__device__ __forceinline__ void mma_tf32(float* c, const uint32_t* a, const uint32_t* b) {
    asm volatile(
        "mma.sync.aligned.m16n8k8.row.col.f32.tf32.tf32.f32 "
        "{%0,%1,%2,%3}, {%4,%5,%6,%7}, {%8,%9}, {%0,%1,%2,%3};"
        : "+f"(c[0]), "+f"(c[1]), "+f"(c[2]), "+f"(c[3])
        : "r"(a[0]), "r"(a[1]), "r"(a[2]), "r"(a[3]), "r"(b[0]), "r"(b[1]));
}

// ---------------- CSR build ----------------
__global__ void hist_kernel(const int* __restrict__ ei) {
    int e = blockIdx.x * 256 + threadIdx.x;
    if (e >= ETOT) return;
    int d = (e < EE) ? ei[EE + e] : (e - EE);
    atomicAdd(&g_deg[d], 1);
}

__global__ void scan1_kernel() {
    __shared__ int sh[256];
    int tid = threadIdx.x;
    int i = blockIdx.x * 256 + tid;
    int v = (i < NN) ? g_deg[i] : 0;
    sh[tid] = v;
    __syncthreads();
#pragma unroll
    for (int off = 1; off < 256; off <<= 1) {
        int t = (tid >= off) ? sh[tid - off] : 0;
        __syncthreads();
        sh[tid] += t;
        __syncthreads();
    }
    if (i < NN) g_off[i] = sh[tid] - v;       // exclusive (local)
    if (tid == 255) g_part[blockIdx.x] = sh[255];
}

__global__ void scan2_kernel() {
    __shared__ int sh[256];
    int tid = threadIdx.x;
    int v = (tid < NB_SCAN) ? g_part[tid] : 0;
    sh[tid] = v;
    __syncthreads();
#pragma unroll
    for (int off = 1; off < 256; off <<= 1) {
        int t = (tid >= off) ? sh[tid - off] : 0;
        __syncthreads();
        sh[tid] += t;
        __syncthreads();
    }
    if (tid < NB_SCAN) g_part[tid] = sh[tid] - v;  // exclusive
}

__global__ void scan3_kernel() {
    int i = blockIdx.x * 256 + threadIdx.x;
    if (i < NN) {
        int o = g_off[i] + g_part[blockIdx.x];
        g_off[i] = o;
        g_cursor[i] = o;
    }
}

__global__ void scatter_kernel(const int* __restrict__ ei) {
    int e = blockIdx.x * 256 + threadIdx.x;
    if (e >= ETOT) return;
    int s, d;
    if (e < EE) { s = ei[e]; d = ei[EE + e]; }
    else        { s = e - EE; d = s; }
    int pos = atomicAdd(&g_cursor[d], 1);
    g_srcs[pos] = s;
}

// ---------------- fused weight: g_wf[f][c] = sum_k Wp[f][k]*W0[k][c]; row FIN = bp@W0 ----------------
__global__ void fusew_kernel(const float* __restrict__ Wp, const float* __restrict__ bp,
                             const float* __restrict__ W0)
{
    int c = threadIdx.x;
    int f = blockIdx.x;
    const float* src = (f < FIN) ? (Wp + f * HH) : bp;
    float acc = 0.f;
#pragma unroll 8
    for (int k = 0; k < HH; k++) acc += src[k] * W0[k * DD + c];
    g_wf[f * DD + c] = acc;
}

// ---------------- tf32 tensor-core GEMM, double-buffered, fused esed / blend ----------------
// C(R x Nc) = A(R x K) @ B(K x Nc) (+bias). 128x128 tile, KTILE=16, 256 threads.
// permT!=0: output row r=(n*permT+t) -> t*permN+n.
// asrc/adst != null: accumulate per-head dots of the BIASED output row into g_esed
//                    (g_esed must be pre-zeroed). Bias is part of hp for layer 0.
// BLEND: A row r = sum_t g_attn[t] * A[t*SLAB + r*K + k] (A = bufB base).
template<int BLEND>
__global__ void __launch_bounds__(256) gemm_tf32(
    const float* __restrict__ A, const float* __restrict__ B,
    const float* __restrict__ bias, float* __restrict__ C,
    int Rows, int K, int Ncols, int permT, int permN,
    const float* __restrict__ asrc, const float* __restrict__ adst)
{
    __shared__ float As[2][16][136];   // [k][row], pad -> frag bank = 8k+row (conflict-free)
    __shared__ float Bs[2][16][136];   // [k][col]
    const int tid = threadIdx.x;
    const int wid = tid >> 5;
    const int lane = tid & 31;
    const int wm = wid >> 2;        // 0..1
    const int wn = wid & 3;         // 0..3
    const int g = lane >> 2;        // 0..7
    const int t4 = lane & 3;        // 0..3
    const int rowBase = blockIdx.y << 7;
    const int colBase = blockIdx.x << 7;

    const int arow = tid >> 1;            // 0..127
    const int ak = (tid & 1) << 3;        // 0 / 8
    const int bk = wid;                   // rows bk, bk+8
    const int bcol = lane << 2;           // 0..124

    float acc[4][4][4];
#pragma unroll
    for (int mi = 0; mi < 4; mi++)
#pragma unroll
        for (int ni = 0; ni < 4; ni++)
#pragma unroll
            for (int q = 0; q < 4; q++) acc[mi][ni][q] = 0.f;

    const int gr = rowBase + arow;
    const bool aOK = gr < Rows;
    const float* Ap = A + (size_t)(aOK ? gr : 0) * K + ak;
    const bool bOK = (colBase + bcol) < Ncols;
    const float* Bp = B + (size_t)bk * Ncols + colBase + bcol;
    const size_t SLAB = (size_t)NN * DD;

    float atw0 = 0.f, atw1 = 0.f, atw2 = 0.f, atw3 = 0.f;
    if (BLEND) { atw0 = g_attn[0]; atw1 = g_attn[1]; atw2 = g_attn[2]; atw3 = g_attn[3]; }

    const int nk = K >> 4;
    float4 ra[2], rb[2];

    auto load_tile = [&](int kt) {
        const int kbase = kt << 4;
#pragma unroll
        for (int i = 0; i < 2; i++) {
            float4 v = make_float4(0.f, 0.f, 0.f, 0.f);
            if (aOK) {
                const float* p = Ap + kbase + i * 4;
                if (BLEND) {
                    float4 u0 = *(const float4*)(p);
                    float4 u1 = *(const float4*)(p + SLAB);
                    float4 u2 = *(const float4*)(p + 2 * SLAB);
                    float4 u3 = *(const float4*)(p + 3 * SLAB);
                    v.x = atw0 * u0.x + atw1 * u1.x + atw2 * u2.x + atw3 * u3.x;
                    v.y = atw0 * u0.y + atw1 * u1.y + atw2 * u2.y + atw3 * u3.y;
                    v.z = atw0 * u0.z + atw1 * u1.z + atw2 * u2.z + atw3 * u3.z;
                    v.w = atw0 * u0.w + atw1 * u1.w + atw2 * u2.w + atw3 * u3.w;
                } else {
                    v = *(const float4*)p;
                }
            }
            ra[i] = v;
            float4 w = make_float4(0.f, 0.f, 0.f, 0.f);
            if (bOK) w = *(const float4*)(Bp + (size_t)(kbase + i * 8) * Ncols);
            rb[i] = w;
        }
    };
    auto store_tile = [&](int buf) {
#pragma unroll
        for (int i = 0; i < 2; i++) {
            int kb = ak + i * 4;
            As[buf][kb + 0][arow] = __uint_as_float(f2tf32(ra[i].x));
            As[buf][kb + 1][arow] = __uint_as_float(f2tf32(ra[i].y));
            As[buf][kb + 2][arow] = __uint_as_float(f2tf32(ra[i].z));
            As[buf][kb + 3][arow] = __uint_as_float(f2tf32(ra[i].w));
            float4 w;
            w.x = __uint_as_float(f2tf32(rb[i].x));
            w.y = __uint_as_float(f2tf32(rb[i].y));
            w.z = __uint_as_float(f2tf32(rb[i].z));
            w.w = __uint_as_float(f2tf32(rb[i].w));
            *(float4*)&Bs[buf][bk + i * 8][bcol] = w;
        }
    };

    load_tile(0);
    store_tile(0);
    __syncthreads();

    for (int kt = 0; kt < nk; kt++) {
        const int buf = kt & 1;
        if (kt + 1 < nk) load_tile(kt + 1);
#pragma unroll
        for (int ks = 0; ks < 2; ks++) {
            const int k0 = ks * 8;
            uint32_t afr[4][4];
            uint32_t bfr[4][2];
#pragma unroll
            for (int mi = 0; mi < 4; mi++) {
                int row = (wm << 6) + (mi << 4) + g;
                afr[mi][0] = __float_as_uint(As[buf][k0 + t4][row]);
                afr[mi][1] = __float_as_uint(As[buf][k0 + t4][row + 8]);
                afr[mi][2] = __float_as_uint(As[buf][k0 + t4 + 4][row]);
                afr[mi][3] = __float_as_uint(As[buf][k0 + t4 + 4][row + 8]);
            }
#pragma unroll
            for (int ni = 0; ni < 4; ni++) {
                int col = (wn << 5) + (ni << 3) + g;
                bfr[ni][0] = __float_as_uint(Bs[buf][k0 + t4][col]);
                bfr[ni][1] = __float_as_uint(Bs[buf][k0 + t4 + 4][col]);
            }
#pragma unroll
            for (int mi = 0; mi < 4; mi++)
#pragma unroll
                for (int ni = 0; ni < 4; ni++)
                    mma_tf32(acc[mi][ni], afr[mi], bfr[ni]);
        }
        if (kt + 1 < nk) {
            store_tile(buf ^ 1);
            __syncthreads();
        }
    }

    // ---- epilogue: bias -> C value, store C, fused es/ed dots on BIASED values ----
#pragma unroll
    for (int mi = 0; mi < 4; mi++) {
        int row0 = rowBase + (wm << 6) + (mi << 4) + g;
        int row1 = row0 + 8;
        int orow0 = -1, orow1 = -1;
        if (row0 < Rows) orow0 = permT ? ((row0 % permT) * permN + row0 / permT) : row0;
        if (row1 < Rows) orow1 = permT ? ((row1 % permT) * permN + row1 / permT) : row1;
        float es0 = 0.f, es1 = 0.f, ed0 = 0.f, ed1 = 0.f;
#pragma unroll
        for (int ni = 0; ni < 4; ni++) {
            int col = colBase + (wn << 5) + (ni << 3) + (t4 << 1);
            if (col < Ncols) {
                float bx = 0.f, by = 0.f;
                if (bias) { bx = bias[col]; by = bias[col + 1]; }
                float c00 = acc[mi][ni][0] + bx;
                float c01 = acc[mi][ni][1] + by;
                float c10 = acc[mi][ni][2] + bx;
                float c11 = acc[mi][ni][3] + by;
                if (orow0 >= 0) {
                    float* cp = C + (size_t)orow0 * Ncols + col;
                    cp[0] = c00;
                    cp[1] = c01;
                }
                if (orow1 >= 0) {
                    float* cp = C + (size_t)orow1 * Ncols + col;
                    cp[0] = c10;
                    cp[1] = c11;
                }
                if (asrc) {
                    float sx = __ldg(asrc + col), sy = __ldg(asrc + col + 1);
                    float dx = __ldg(adst + col), dy = __ldg(adst + col + 1);
                    es0 += c00 * sx + c01 * sy;
                    ed0 += c00 * dx + c01 * dy;
                    es1 += c10 * sx + c11 * sy;
                    ed1 += c10 * dx + c11 * dy;
                }
            }
        }
        if (asrc) {
            es0 += __shfl_xor_sync(0xffffffffu, es0, 1);
            es0 += __shfl_xor_sync(0xffffffffu, es0, 2);
            es1 += __shfl_xor_sync(0xffffffffu, es1, 1);
            es1 += __shfl_xor_sync(0xffffffffu, es1, 2);
            ed0 += __shfl_xor_sync(0xffffffffu, ed0, 1);
            ed0 += __shfl_xor_sync(0xffffffffu, ed0, 2);
            ed1 += __shfl_xor_sync(0xffffffffu, ed1, 1);
            ed1 += __shfl_xor_sync(0xffffffffu, ed1, 2);
            if (t4 == 0) {
                int head = (colBase + (wn << 5)) >> 6;
                if (orow0 >= 0) {
                    atomicAdd(&g_esed[(size_t)orow0 * HEADS + head], es0);
                    atomicAdd(&g_esed[ESZ + (size_t)orow0 * HEADS + head], ed0);
                }
                if (orow1 >= 0) {
                    atomicAdd(&g_esed[(size_t)orow1 * HEADS + head], es1);
                    atomicAdd(&g_esed[ESZ + (size_t)orow1 * HEADS + head], ed1);
                }
            }
        }
    }
}

// ---------------- fused softmax + aggregation: warp per (t, dst) ----------------
__global__ void __launch_bounds__(256) agg_kernel(const float* __restrict__ bias,
                                                  float* __restrict__ out)
{
    int gw = (blockIdx.x * 256 + threadIdx.x) >> 5;
    int lane = threadIdx.x & 31;
    if (gw >= TT * NN) return;
    int t = gw / NN;
    int d = gw - t * NN;
    int base = g_off[d];
    int deg = g_deg[d];
    const size_t tN = (size_t)t * NN;
    const float* edp = g_esed + ESZ + (size_t)gw * HEADS;

    // ---- pass 1: z per head (8 edges x 4 heads per iteration) ----
    float ed_q = __ldg(edp + (lane & 3));
    float z = 0.f;
    for (int j0 = 0; j0 < deg; j0 += 8) {
        int j = j0 + (lane >> 2);
        if (j < deg) {
            int s = g_srcs[base + j];
            float es = __ldg(g_esed + (tN + s) * HEADS + (lane & 3));
            float v = es + ed_q;
            v = v > 0.f ? v : NEG_SLOPE * v;
            z += expf(v);
        }
    }
    z += __shfl_xor_sync(0xffffffffu, z, 4);
    z += __shfl_xor_sync(0xffffffffu, z, 8);
    z += __shfl_xor_sync(0xffffffffu, z, 16);
    int myh = lane >> 3;
    float zh = __shfl_sync(0xffffffffu, z, myh);
    float zinv = 1.f / (zh + 1e-16f);
    float edh = __ldg(edp + myh);

    // ---- pass 2: weighted accumulation ----
    float4 a0 = make_float4(0.f, 0.f, 0.f, 0.f);
    float4 a1 = make_float4(0.f, 0.f, 0.f, 0.f);
    for (int j = 0; j < deg; j++) {
        int s = g_srcs[base + j];
        float es = __ldg(g_esed + (tN + s) * HEADS + myh);
        float v = es + edh;
        v = v > 0.f ? v : NEG_SLOPE * v;
        float alpha = expf(v) * zinv;
        const float4* r = (const float4*)(g_hp + (tN + s) * DD) + lane * 2;
        float4 u0 = __ldg(r);
        float4 u1 = __ldg(r + 1);
        a0.x += alpha * u0.x; a0.y += alpha * u0.y;
        a0.z += alpha * u0.z; a0.w += alpha * u0.w;
        a1.x += alpha * u1.x; a1.y += alpha * u1.y;
        a1.z += alpha * u1.z; a1.w += alpha * u1.w;
    }

    // ---- epilogue: bias + ELU, single write ----
    const float4* bp4 = (const float4*)bias + lane * 2;
    float4 b0v = __ldg(bp4), b1v = __ldg(bp4 + 1);
    float4 o0, o1;
    o0.x = eluf(a0.x + b0v.x); o0.y = eluf(a0.y + b0v.y);
    o0.z = eluf(a0.z + b0v.z); o0.w = eluf(a0.w + b0v.w);
    o1.x = eluf(a1.x + b1v.x); o1.y = eluf(a1.y + b1v.y);
    o1.z = eluf(a1.z + b1v.z); o1.w = eluf(a1.w + b1v.w);
    float4* op = (float4*)(out + (size_t)gw * DD) + lane * 2;
    op[0] = o0;
    op[1] = o1;
}

// ---------------- per-t column sums of embs (bufB) ----------------
__global__ void __launch_bounds__(256) colsum_kernel()
{
    int t = blockIdx.y;
    int c = threadIdx.x;
    float s = 0.f;
    for (int n = blockIdx.x; n < NN; n += gridDim.x)
        s += g_bufB[((size_t)t * NN + n) * DD + c];
    atomicAdd(&g_colsum[t * DD + c], s);
}

// ---------------- temporal attention weights (single block) ----------------
__global__ void __launch_bounds__(256) attn_kernel(
    const float* __restrict__ Wq, const float* __restrict__ bq,
    const float* __restrict__ Wk, const float* __restrict__ bk)
{
    __shared__ float mean[TT][DD];
    __shared__ float Kt[TT][DD];
    __shared__ float Qv[DD];
    __shared__ float red[256];
    __shared__ float sc[TT];
    int c = threadIdx.x;
#pragma unroll
    for (int t = 0; t < TT; t++)
        mean[t][c] = g_colsum[t * DD + c] * (1.0f / (float)NN);
    __syncthreads();
#pragma unroll
    for (int t = 0; t < TT; t++) {
        float acc = bk[c];
        for (int f = 0; f < DD; f++) acc += mean[t][f] * Wk[f * DD + c];
        Kt[t][c] = acc;
    }
    {
        float acc = bq[c];
        for (int f = 0; f < DD; f++) acc += mean[TT - 1][f] * Wq[f * DD + c];
        Qv[c] = acc;
    }
    __syncthreads();
    for (int t = 0; t < TT; t++) {
        red[c] = Qv[c] * Kt[t][c];
        __syncthreads();
        for (int off = 128; off > 0; off >>= 1) {
            if (c < off) red[c] += red[c + off];
            __syncthreads();
        }
        if (c == 0) sc[t] = red[0] * (1.0f / 16.0f);   // 1/sqrt(256)
        __syncthreads();
    }
    if (c == 0) {
        float m = fmaxf(fmaxf(sc[0], sc[1]), fmaxf(sc[2], sc[3]));
        float w0 = expf(sc[0] - m), w1 = expf(sc[1] - m);
        float w2 = expf(sc[2] - m), w3 = expf(sc[3] - m);
        float inv = 1.0f / (w0 + w1 + w2 + w3);
        g_attn[0] = w0 * inv; g_attn[1] = w1 * inv;
        g_attn[2] = w2 * inv; g_attn[3] = w3 * inv;
    }
}

// ---------------- launch ----------------
extern "C" void kernel_launch(void* const* d_in, const int* in_sizes, int n_in,
                              void* d_out, int out_size)
{
    const float* x      = (const float*)d_in[0];
    const int*   ei     = (const int*)  d_in[1];
    const float* Wp     = (const float*)d_in[2];
    const float* bp     = (const float*)d_in[3];
    const float* W0     = (const float*)d_in[4];
    const float* a_src0 = (const float*)d_in[5];
    const float* a_dst0 = (const float*)d_in[6];
    const float* b0     = (const float*)d_in[7];
    const float* W1     = (const float*)d_in[8];
    const float* a_src1 = (const float*)d_in[9];
    const float* a_dst1 = (const float*)d_in[10];
    const float* b1     = (const float*)d_in[11];
    const float* Wq     = (const float*)d_in[12];
    const float* bq     = (const float*)d_in[13];
    const float* Wk     = (const float*)d_in[14];
    const float* bk     = (const float*)d_in[15];
    const float* Wv     = (const float*)d_in[16];
    const float* bv     = (const float*)d_in[17];

    float *hp, *bufA, *bufB, *esed, *cs, *wf;
    int *degp;
    cudaGetSymbolAddress((void**)&hp,   g_hp);
    cudaGetSymbolAddress((void**)&bufA, g_bufA);
    cudaGetSymbolAddress((void**)&bufB, g_bufB);
    cudaGetSymbolAddress((void**)&esed, g_esed);
    cudaGetSymbolAddress((void**)&cs,   g_colsum);
    cudaGetSymbolAddress((void**)&wf,   g_wf);
    cudaGetSymbolAddress((void**)&degp, g_deg);

    const int rowsTN = TT * NN;            // 120000
    const int edges  = ETOT;               // 270000
    const int gy = (rowsTN + 127) / 128;   // 938
    const int esed4 = 2 * ESZ / 4;         // 480000

    // ---- CSR build (graph shared across t and both layers) ----
    zero_kernel<<<(NN / 4 + 255) / 256, 256>>>((float4*)degp, NN / 4);
    hist_kernel<<<(edges + 255) / 256, 256>>>(ei);
    scan1_kernel<<<NB_SCAN, 256>>>();
    scan2_kernel<<<1, 256>>>();
    scan3_kernel<<<NB_SCAN, 256>>>();
    scatter_kernel<<<(edges + 255) / 256, 256>>>(ei);

    // ---- fused first-layer weight: Wf = Wp@W0 (+ bias row bp@W0) ----
    fusew_kernel<<<FIN + 1, 256>>>(Wp, bp, W0);

    // ---- GAT layer 0: hp = x @ Wf + bf, rows (n,t) -> (t,n); es/ed fused ----
    zero_kernel<<<(esed4 + 255) / 256, 256>>>((float4*)esed, esed4);
    gemm_tf32<0><<<dim3(2, gy), 256>>>(x, wf, wf + FIN * DD, hp, rowsTN, FIN, DD,
                                       TT, NN, a_src0, a_dst0);
    agg_kernel<<<(rowsTN + 7) / 8, 256>>>(b0, bufA);

    // ---- GAT layer 1 ----
    zero_kernel<<<(esed4 + 255) / 256, 256>>>((float4*)esed, esed4);
    gemm_tf32<0><<<dim3(2, gy), 256>>>(bufA, W1, nullptr, hp, rowsTN, DD, DD,
                                       0, 0, a_src1, a_dst1);
    agg_kernel<<<(rowsTN + 7) / 8, 256>>>(b1, bufB);

    // ---- temporal attention ----
    zero_kernel<<<1, 256>>>((float4*)cs, TT * DD / 4);
    colsum_kernel<<<dim3(128, TT), 256>>>();
    attn_kernel<<<1, 256>>>(Wq, bq, Wk, bk);

    // ---- out = (sum_t attn[t] * embs_t) @ Wv + bv  (blend fused into A-load) ----
    gemm_tf32<1><<<dim3(2, (NN + 127) / 128), 256>>>(bufB, Wv, bv, (float*)d_out,
                                                     NN, DD, DD, 0, 0, nullptr, nullptr);
}

// round 9
// speedup vs baseline: 1.0917x; 1.0917x over previous
#include <cuda_runtime.h>
#include <math.h>
#include <stdint.h>

#define NN 30000
#define TT 4
#define FIN 256
#define HH 64
#define HEADS 4
#define DD 256
#define EE 240000
#define ETOT 270000            // EE + NN self loops
#define NEG_SLOPE 0.2f
#define NB_SCAN 118            // ceil(NN/256)
#define ESZ (TT * NN * HEADS)

// ---------------- scratch (device globals: allocation-free) ----------------
__device__ __align__(16) float g_h0[TT * NN * HH];     // xWp output, (t,n) order
__device__ __align__(16) float g_hp[TT * NN * DD];     // per-layer hp = h @ W
__device__ __align__(16) float g_bufA[TT * NN * DD];   // layer0 output (post ELU)
__device__ __align__(16) float g_bufB[TT * NN * DD];   // layer1 output (embs)
__device__ __align__(16) float g_esed[2 * ESZ];        // es at 0, ed at ESZ
__device__ __align__(16) float g_colsum[TT * DD];
__device__ float g_attn[TT];
// CSR
__device__ int g_deg[NN];
__device__ int g_off[NN];
__device__ int g_cursor[NN];
__device__ int g_part[256];
__device__ int g_srcs[ETOT];

// ---------------- utility ----------------
__global__ void zero_kernel(float4* __restrict__ p, int n4) {
    int i = blockIdx.x * blockDim.x + threadIdx.x;
    if (i < n4) p[i] = make_float4(0.f, 0.f, 0.f, 0.f);
}

__device__ __forceinline__ float eluf(float x) { return x > 0.f ? x : expm1f(x); }

__device__ __forceinline__ uint32_t f2tf32(float x) {
    uint32_t r;
    asm("cvt.rna.tf32.f32 %0, %1;" : "=r"(r) : "f"(x));
    return r;
}

__device__ __forceinline__ void mma_tf32(float* c, const uint32_t* a, const uint32_t* b) {
    asm volatile(
        "mma.sync.aligned.m16n8k8.row.col.f32.tf32.tf32.f32 "
        "{%0,%1,%2,%3}, {%4,%5,%6,%7}, {%8,%9}, {%0,%1,%2,%3};"
        : "+f"(c[0]), "+f"(c[1]), "+f"(c[2]), "+f"(c[3])
        : "r"(a[0]), "r"(a[1]), "r"(a[2]), "r"(a[3]), "r"(b[0]), "r"(b[1]));
}

// ---------------- CSR build ----------------
__global__ void hist_kernel(const int* __restrict__ ei) {
    int e = blockIdx.x * 256 + threadIdx.x;
    if (e >= ETOT) return;
    int d = (e < EE) ? ei[EE + e] : (e - EE);
    atomicAdd(&g_deg[d], 1);
}

__global__ void scan1_kernel() {
    __shared__ int sh[256];
    int tid = threadIdx.x;
    int i = blockIdx.x * 256 + tid;
    int v = (i < NN) ? g_deg[i] : 0;
    sh[tid] = v;
    __syncthreads();
#pragma unroll
    for (int off = 1; off < 256; off <<= 1) {
        int t = (tid >= off) ? sh[tid - off] : 0;
        __syncthreads();
        sh[tid] += t;
        __syncthreads();
    }
    if (i < NN) g_off[i] = sh[tid] - v;       // exclusive (local)
    if (tid == 255) g_part[blockIdx.x] = sh[255];
}

__global__ void scan2_kernel() {
    __shared__ int sh[256];
    int tid = threadIdx.x;
    int v = (tid < NB_SCAN) ? g_part[tid] : 0;
    sh[tid] = v;
    __syncthreads();
#pragma unroll
    for (int off = 1; off < 256; off <<= 1) {
        int t = (tid >= off) ? sh[tid - off] : 0;
        __syncthreads();
        sh[tid] += t;
        __syncthreads();
    }
    if (tid < NB_SCAN) g_part[tid] = sh[tid] - v;  // exclusive
}

__global__ void scan3_kernel() {
    int i = blockIdx.x * 256 + threadIdx.x;
    if (i < NN) {
        int o = g_off[i] + g_part[blockIdx.x];
        g_off[i] = o;
        g_cursor[i] = o;
    }
}

__global__ void scatter_kernel(const int* __restrict__ ei) {
    int e = blockIdx.x * 256 + threadIdx.x;
    if (e >= ETOT) return;
    int s, d;
    if (e < EE) { s = ei[e]; d = ei[EE + e]; }
    else        { s = e - EE; d = s; }
    int pos = atomicAdd(&g_cursor[d], 1);
    g_srcs[pos] = s;
}

// ---------------- tf32 tensor-core GEMM, double-buffered, fused esed / blend ----------------
// C(R x Nc) = A(R x K) @ B(K x Nc) (+bias). 128x128 tile, KTILE=16, 256 threads.
// permT!=0: output row r=(n*permT+t) -> t*permN+n.
// asrc/adst != null: accumulate per-head dots of the BIASED output row into g_esed
//                    (g_esed must be pre-zeroed).
// BLEND: A row r = sum_t g_attn[t] * A[t*SLAB + r*K + k] (A = bufB base).
template<int BLEND>
__global__ void __launch_bounds__(256) gemm_tf32(
    const float* __restrict__ A, const float* __restrict__ B,
    const float* __restrict__ bias, float* __restrict__ C,
    int Rows, int K, int Ncols, int permT, int permN,
    const float* __restrict__ asrc, const float* __restrict__ adst)
{
    __shared__ float As[2][16][136];   // [k][row], pad -> frag bank = 8k+row (conflict-free)
    __shared__ float Bs[2][16][136];   // [k][col]
    const int tid = threadIdx.x;
    const int wid = tid >> 5;
    const int lane = tid & 31;
    const int wm = wid >> 2;        // 0..1
    const int wn = wid & 3;         // 0..3
    const int g = lane >> 2;        // 0..7
    const int t4 = lane & 3;        // 0..3
    const int rowBase = blockIdx.y << 7;
    const int colBase = blockIdx.x << 7;

    const int arow = tid >> 1;            // 0..127
    const int ak = (tid & 1) << 3;        // 0 / 8
    const int bk = wid;                   // rows bk, bk+8
    const int bcol = lane << 2;           // 0..124

    float acc[4][4][4];
#pragma unroll
    for (int mi = 0; mi < 4; mi++)
#pragma unroll
        for (int ni = 0; ni < 4; ni++)
#pragma unroll
            for (int q = 0; q < 4; q++) acc[mi][ni][q] = 0.f;

    const int gr = rowBase + arow;
    const bool aOK = gr < Rows;
    const float* Ap = A + (size_t)(aOK ? gr : 0) * K + ak;
    const bool bOK = (colBase + bcol) < Ncols;
    const float* Bp = B + (size_t)bk * Ncols + colBase + bcol;
    const size_t SLAB = (size_t)NN * DD;

    float atw0 = 0.f, atw1 = 0.f, atw2 = 0.f, atw3 = 0.f;
    if (BLEND) { atw0 = g_attn[0]; atw1 = g_attn[1]; atw2 = g_attn[2]; atw3 = g_attn[3]; }

    const int nk = K >> 4;
    float4 ra[2], rb[2];

    auto load_tile = [&](int kt) {
        const int kbase = kt << 4;
#pragma unroll
        for (int i = 0; i < 2; i++) {
            float4 v = make_float4(0.f, 0.f, 0.f, 0.f);
            if (aOK) {
                const float* p = Ap + kbase + i * 4;
                if (BLEND) {
                    float4 u0 = *(const float4*)(p);
                    float4 u1 = *(const float4*)(p + SLAB);
                    float4 u2 = *(const float4*)(p + 2 * SLAB);
                    float4 u3 = *(const float4*)(p + 3 * SLAB);
                    v.x = atw0 * u0.x + atw1 * u1.x + atw2 * u2.x + atw3 * u3.x;
                    v.y = atw0 * u0.y + atw1 * u1.y + atw2 * u2.y + atw3 * u3.y;
                    v.z = atw0 * u0.z + atw1 * u1.z + atw2 * u2.z + atw3 * u3.z;
                    v.w = atw0 * u0.w + atw1 * u1.w + atw2 * u2.w + atw3 * u3.w;
                } else {
                    v = *(const float4*)p;
                }
            }
            ra[i] = v;
            float4 w = make_float4(0.f, 0.f, 0.f, 0.f);
            if (bOK) w = *(const float4*)(Bp + (size_t)(kbase + i * 8) * Ncols);
            rb[i] = w;
        }
    };
    auto store_tile = [&](int buf) {
#pragma unroll
        for (int i = 0; i < 2; i++) {
            int kb = ak + i * 4;
            As[buf][kb + 0][arow] = __uint_as_float(f2tf32(ra[i].x));
            As[buf][kb + 1][arow] = __uint_as_float(f2tf32(ra[i].y));
            As[buf][kb + 2][arow] = __uint_as_float(f2tf32(ra[i].z));
            As[buf][kb + 3][arow] = __uint_as_float(f2tf32(ra[i].w));
            float4 w;
            w.x = __uint_as_float(f2tf32(rb[i].x));
            w.y = __uint_as_float(f2tf32(rb[i].y));
            w.z = __uint_as_float(f2tf32(rb[i].z));
            w.w = __uint_as_float(f2tf32(rb[i].w));
            *(float4*)&Bs[buf][bk + i * 8][bcol] = w;
        }
    };

    load_tile(0);
    store_tile(0);
    __syncthreads();

    for (int kt = 0; kt < nk; kt++) {
        const int buf = kt & 1;
        if (kt + 1 < nk) load_tile(kt + 1);
#pragma unroll
        for (int ks = 0; ks < 2; ks++) {
            const int k0 = ks * 8;
            uint32_t afr[4][4];
            uint32_t bfr[4][2];
#pragma unroll
            for (int mi = 0; mi < 4; mi++) {
                int row = (wm << 6) + (mi << 4) + g;
                afr[mi][0] = __float_as_uint(As[buf][k0 + t4][row]);
                afr[mi][1] = __float_as_uint(As[buf][k0 + t4][row + 8]);
                afr[mi][2] = __float_as_uint(As[buf][k0 + t4 + 4][row]);
                afr[mi][3] = __float_as_uint(As[buf][k0 + t4 + 4][row + 8]);
            }
#pragma unroll
            for (int ni = 0; ni < 4; ni++) {
                int col = (wn << 5) + (ni << 3) + g;
                bfr[ni][0] = __float_as_uint(Bs[buf][k0 + t4][col]);
                bfr[ni][1] = __float_as_uint(Bs[buf][k0 + t4 + 4][col]);
            }
#pragma unroll
            for (int mi = 0; mi < 4; mi++)
#pragma unroll
                for (int ni = 0; ni < 4; ni++)
                    mma_tf32(acc[mi][ni], afr[mi], bfr[ni]);
        }
        if (kt + 1 < nk) {
            store_tile(buf ^ 1);
            __syncthreads();
        }
    }

    // ---- epilogue: bias -> C value, store C, fused es/ed dots on biased values ----
#pragma unroll
    for (int mi = 0; mi < 4; mi++) {
        int row0 = rowBase + (wm << 6) + (mi << 4) + g;
        int row1 = row0 + 8;
        int orow0 = -1, orow1 = -1;
        if (row0 < Rows) orow0 = permT ? ((row0 % permT) * permN + row0 / permT) : row0;
        if (row1 < Rows) orow1 = permT ? ((row1 % permT) * permN + row1 / permT) : row1;
        float es0 = 0.f, es1 = 0.f, ed0 = 0.f, ed1 = 0.f;
#pragma unroll
        for (int ni = 0; ni < 4; ni++) {
            int col = colBase + (wn << 5) + (ni << 3) + (t4 << 1);
            if (col < Ncols) {
                float bx = 0.f, by = 0.f;
                if (bias) { bx = bias[col]; by = bias[col + 1]; }
                float c00 = acc[mi][ni][0] + bx;
                float c01 = acc[mi][ni][1] + by;
                float c10 = acc[mi][ni][2] + bx;
                float c11 = acc[mi][ni][3] + by;
                if (orow0 >= 0) {
                    float* cp = C + (size_t)orow0 * Ncols + col;
                    cp[0] = c00;
                    cp[1] = c01;
                }
                if (orow1 >= 0) {
                    float* cp = C + (size_t)orow1 * Ncols + col;
                    cp[0] = c10;
                    cp[1] = c11;
                }
                if (asrc) {
                    float sx = __ldg(asrc + col), sy = __ldg(asrc + col + 1);
                    float dx = __ldg(adst + col), dy = __ldg(adst + col + 1);
                    es0 += c00 * sx + c01 * sy;
                    ed0 += c00 * dx + c01 * dy;
                    es1 += c10 * sx + c11 * sy;
                    ed1 += c10 * dx + c11 * dy;
                }
            }
        }
        if (asrc) {
            es0 += __shfl_xor_sync(0xffffffffu, es0, 1);
            es0 += __shfl_xor_sync(0xffffffffu, es0, 2);
            es1 += __shfl_xor_sync(0xffffffffu, es1, 1);
            es1 += __shfl_xor_sync(0xffffffffu, es1, 2);
            ed0 += __shfl_xor_sync(0xffffffffu, ed0, 1);
            ed0 += __shfl_xor_sync(0xffffffffu, ed0, 2);
            ed1 += __shfl_xor_sync(0xffffffffu, ed1, 1);
            ed1 += __shfl_xor_sync(0xffffffffu, ed1, 2);
            if (t4 == 0) {
                int head = (colBase + (wn << 5)) >> 6;
                if (orow0 >= 0) {
                    atomicAdd(&g_esed[(size_t)orow0 * HEADS + head], es0);
                    atomicAdd(&g_esed[ESZ + (size_t)orow0 * HEADS + head], ed0);
                }
                if (orow1 >= 0) {
                    atomicAdd(&g_esed[(size_t)orow1 * HEADS + head], es1);
                    atomicAdd(&g_esed[ESZ + (size_t)orow1 * HEADS + head], ed1);
                }
            }
        }
    }
}

// ---------------- fused softmax + aggregation, SINGLE PASS: warp per (t, dst) ----------------
// out = ELU( (sum_e w_e * hp[src]) / (z + 1e-16) + bias ),  w_e = exp(leaky(es+ed)), z = sum w_e
__global__ void __launch_bounds__(256) agg_kernel(const float* __restrict__ bias,
                                                  float* __restrict__ out)
{
    int gw = (blockIdx.x * 256 + threadIdx.x) >> 5;
    int lane = threadIdx.x & 31;
    if (gw >= TT * NN) return;
    int t = gw / NN;
    int d = gw - t * NN;
    int base = g_off[d];
    int deg = g_deg[d];
    const size_t tN = (size_t)t * NN;
    int myh = lane >> 3;                   // head of my 8 output cols
    float edh = __ldg(g_esed + ESZ + (size_t)gw * HEADS + myh);

    float z = 0.f;
    float4 a0 = make_float4(0.f, 0.f, 0.f, 0.f);
    float4 a1 = make_float4(0.f, 0.f, 0.f, 0.f);
    for (int j = 0; j < deg; j++) {
        int s = g_srcs[base + j];
        float es = __ldg(g_esed + (tN + s) * HEADS + myh);
        float v = es + edh;
        v = v > 0.f ? v : NEG_SLOPE * v;
        float w = expf(v);
        z += w;
        const float4* r = (const float4*)(g_hp + (tN + s) * DD) + lane * 2;
        float4 u0 = __ldg(r);
        float4 u1 = __ldg(r + 1);
        a0.x += w * u0.x; a0.y += w * u0.y;
        a0.z += w * u0.z; a0.w += w * u0.w;
        a1.x += w * u1.x; a1.y += w * u1.y;
        a1.z += w * u1.z; a1.w += w * u1.w;
    }
    float zinv = 1.f / (z + 1e-16f);

    // ---- epilogue: normalize + bias + ELU, single write ----
    const float4* bp4 = (const float4*)bias + lane * 2;
    float4 b0v = __ldg(bp4), b1v = __ldg(bp4 + 1);
    float4 o0, o1;
    o0.x = eluf(a0.x * zinv + b0v.x); o0.y = eluf(a0.y * zinv + b0v.y);
    o0.z = eluf(a0.z * zinv + b0v.z); o0.w = eluf(a0.w * zinv + b0v.w);
    o1.x = eluf(a1.x * zinv + b1v.x); o1.y = eluf(a1.y * zinv + b1v.y);
    o1.z = eluf(a1.z * zinv + b1v.z); o1.w = eluf(a1.w * zinv + b1v.w);
    float4* op = (float4*)(out + (size_t)gw * DD) + lane * 2;
    op[0] = o0;
    op[1] = o1;
}

// ---------------- per-t column sums of embs (bufB) ----------------
__global__ void __launch_bounds__(256) colsum_kernel()
{
    int t = blockIdx.y;
    int c = threadIdx.x;
    float s = 0.f;
    for (int n = blockIdx.x; n < NN; n += gridDim.x)
        s += g_bufB[((size_t)t * NN + n) * DD + c];
    atomicAdd(&g_colsum[t * DD + c], s);
}

// ---------------- temporal attention weights (single block) ----------------
__global__ void __launch_bounds__(256) attn_kernel(
    const float* __restrict__ Wq, const float* __restrict__ bq,
    const float* __restrict__ Wk, const float* __restrict__ bk)
{
    __shared__ float mean[TT][DD];
    __shared__ float Kt[TT][DD];
    __shared__ float Qv[DD];
    __shared__ float red[256];
    __shared__ float sc[TT];
    int c = threadIdx.x;
#pragma unroll
    for (int t = 0; t < TT; t++)
        mean[t][c] = g_colsum[t * DD + c] * (1.0f / (float)NN);
    __syncthreads();
#pragma unroll
    for (int t = 0; t < TT; t++) {
        float acc = bk[c];
        for (int f = 0; f < DD; f++) acc += mean[t][f] * Wk[f * DD + c];
        Kt[t][c] = acc;
    }
    {
        float acc = bq[c];
        for (int f = 0; f < DD; f++) acc += mean[TT - 1][f] * Wq[f * DD + c];
        Qv[c] = acc;
    }
    __syncthreads();
    for (int t = 0; t < TT; t++) {
        red[c] = Qv[c] * Kt[t][c];
        __syncthreads();
        for (int off = 128; off > 0; off >>= 1) {
            if (c < off) red[c] += red[c + off];
            __syncthreads();
        }
        if (c == 0) sc[t] = red[0] * (1.0f / 16.0f);   // 1/sqrt(256)
        __syncthreads();
    }
    if (c == 0) {
        float m = fmaxf(fmaxf(sc[0], sc[1]), fmaxf(sc[2], sc[3]));
        float w0 = expf(sc[0] - m), w1 = expf(sc[1] - m);
        float w2 = expf(sc[2] - m), w3 = expf(sc[3] - m);
        float inv = 1.0f / (w0 + w1 + w2 + w3);
        g_attn[0] = w0 * inv; g_attn[1] = w1 * inv;
        g_attn[2] = w2 * inv; g_attn[3] = w3 * inv;
    }
}

// ---------------- launch ----------------
extern "C" void kernel_launch(void* const* d_in, const int* in_sizes, int n_in,
                              void* d_out, int out_size)
{
    const float* x      = (const float*)d_in[0];
    const int*   ei     = (const int*)  d_in[1];
    const float* Wp     = (const float*)d_in[2];
    const float* bp     = (const float*)d_in[3];
    const float* W0     = (const float*)d_in[4];
    const float* a_src0 = (const float*)d_in[5];
    const float* a_dst0 = (const float*)d_in[6];
    const float* b0     = (const float*)d_in[7];
    const float* W1     = (const float*)d_in[8];
    const float* a_src1 = (const float*)d_in[9];
    const float* a_dst1 = (const float*)d_in[10];
    const float* b1     = (const float*)d_in[11];
    const float* Wq     = (const float*)d_in[12];
    const float* bq     = (const float*)d_in[13];
    const float* Wk     = (const float*)d_in[14];
    const float* bk     = (const float*)d_in[15];
    const float* Wv     = (const float*)d_in[16];
    const float* bv     = (const float*)d_in[17];

    float *h0, *hp, *bufA, *bufB, *esed, *cs;
    int *degp;
    cudaGetSymbolAddress((void**)&h0,   g_h0);
    cudaGetSymbolAddress((void**)&hp,   g_hp);
    cudaGetSymbolAddress((void**)&bufA, g_bufA);
    cudaGetSymbolAddress((void**)&bufB, g_bufB);
    cudaGetSymbolAddress((void**)&esed, g_esed);
    cudaGetSymbolAddress((void**)&cs,   g_colsum);
    cudaGetSymbolAddress((void**)&degp, g_deg);

    const int rowsTN = TT * NN;            // 120000
    const int edges  = ETOT;               // 270000
    const int gy = (rowsTN + 127) / 128;   // 938
    const int esed4 = 2 * ESZ / 4;         // 480000

    // ---- CSR build (graph shared across t and both layers) ----
    zero_kernel<<<(NN / 4 + 255) / 256, 256>>>((float4*)degp, NN / 4);
    hist_kernel<<<(edges + 255) / 256, 256>>>(ei);
    scan1_kernel<<<NB_SCAN, 256>>>();
    scan2_kernel<<<1, 256>>>();
    scan3_kernel<<<NB_SCAN, 256>>>();
    scatter_kernel<<<(edges + 255) / 256, 256>>>(ei);

    // ---- h0(t,n) = x[n,t] @ Wp + bp  (64-wide, bias folded here, perm output) ----
    gemm_tf32<0><<<dim3(1, gy), 256>>>(x, Wp, bp, h0, rowsTN, FIN, HH,
                                       TT, NN, nullptr, nullptr);

    // ---- GAT layer 0: hp = h0 @ W0 (K=64), es/ed fused on outputs ----
    zero_kernel<<<(esed4 + 255) / 256, 256>>>((float4*)esed, esed4);
    gemm_tf32<0><<<dim3(2, gy), 256>>>(h0, W0, nullptr, hp, rowsTN, HH, DD,
                                       0, 0, a_src0, a_dst0);
    agg_kernel<<<(rowsTN + 7) / 8, 256>>>(b0, bufA);

    // ---- GAT layer 1 ----
    zero_kernel<<<(esed4 + 255) / 256, 256>>>((float4*)esed, esed4);
    gemm_tf32<0><<<dim3(2, gy), 256>>>(bufA, W1, nullptr, hp, rowsTN, DD, DD,
                                       0, 0, a_src1, a_dst1);
    agg_kernel<<<(rowsTN + 7) / 8, 256>>>(b1, bufB);

    // ---- temporal attention ----
    zero_kernel<<<1, 256>>>((float4*)cs, TT * DD / 4);
    colsum_kernel<<<dim3(128, TT), 256>>>();
    attn_kernel<<<1, 256>>>(Wq, bq, Wk, bk);

    // ---- out = (sum_t attn[t] * embs_t) @ Wv + bv  (blend fused into A-load) ----
    gemm_tf32<1><<<dim3(2, (NN + 127) / 128), 256>>>(bufB, Wv, bv, (float*)d_out,
                                                     NN, DD, DD, 0, 0, nullptr, nullptr);
}